// round 8
// baseline (speedup 1.0000x reference)
#include <cuda_runtime.h>
#include <float.h>
#include <math.h>
#include <stdint.h>

#define BB 8
#define LL 2048
#define DIN 256
#define DATT 128

// zipped scratch for projected/ELU'd (tf32-rounded) matrices.
// Within each 128-float row, index k is stored at ZP(k):
//   one LDS.128 at (s2*16 + t*4) returns the mma fragment elements
//   {k=16*s2+t, 16*s2+4+t, 16*s2+8+t, 16*s2+12+t}  (two k-steps).
__device__ float g_inp[BB * LL * DATT];   // elu(context @ W_in), zipped
__device__ float g_mem[BB * LL * DATT];   // elu(query  @ W_mem), zipped

__device__ __host__ __forceinline__ int ZP(int k) {
    return (k >> 4) * 16 + (k & 3) * 4 + ((k >> 3) & 1) * 2 + ((k >> 2) & 1);
}

__device__ __forceinline__ float elu01(float v) {
    return v > 0.0f ? v : 0.01f * expm1f(v);
}
__device__ __forceinline__ float f2tf(float v) {
    uint32_t r;
    asm("cvt.rna.tf32.f32 %0, %1;" : "=r"(r) : "f"(v));
    return __uint_as_float(r);
}
__device__ __forceinline__ float fex2(float x) {
    float r;
    asm("ex2.approx.f32 %0, %1;" : "=f"(r) : "f"(x));
    return r;
}
__device__ __forceinline__ uint32_t fu(float v) { return __float_as_uint(v); }

__device__ __forceinline__ void mma8(float d[4],
                                     uint32_t a0, uint32_t a1, uint32_t a2, uint32_t a3,
                                     uint32_t b0, uint32_t b1) {
    asm volatile(
        "mma.sync.aligned.m16n8k8.row.col.f32.tf32.tf32.f32 "
        "{%0,%1,%2,%3},{%4,%5,%6,%7},{%8,%9},{%0,%1,%2,%3};\n"
        : "+f"(d[0]), "+f"(d[1]), "+f"(d[2]), "+f"(d[3])
        : "r"(a0), "r"(a1), "r"(a2), "r"(a3), "r"(b0), "r"(b1));
}

__device__ __forceinline__ void cpa16(uint32_t dst, const float* src) {
    asm volatile("cp.async.cg.shared.global [%0], [%1], 16;\n" :: "r"(dst), "l"(src));
}
#define CPA_COMMIT() asm volatile("cp.async.commit_group;\n" ::: "memory")
#define CPA_WAIT0()  asm volatile("cp.async.wait_group 0;\n" ::: "memory")

// ---------------------------------------------------------------------------
// Kernel 1: projections on tensor cores.  grid = (16384/128, 2), block = 256.
// O = tf32_round(elu(X @ W)) stored ZIPPED per row.
// ---------------------------------------------------------------------------
__global__ __launch_bounds__(256) void proj_kernel(
    const float* __restrict__ ctx, const float* __restrict__ qry,
    const float* __restrict__ Win, const float* __restrict__ Wmem)
{
    const int which = blockIdx.y;
    const float* X = (which == 0) ? ctx : qry;
    const float* W = (which == 0) ? Win : Wmem;
    float* O = (which == 0) ? g_inp : g_mem;

    __shared__ float Xs[128 * 36];
    __shared__ float Ws[32 * 136];

    const int tid  = threadIdx.x;
    const int w    = tid >> 5;
    const int lane = tid & 31;
    const int g = lane >> 2;
    const int t = lane & 3;
    const int r0 = (w >> 1) * 32;
    const int n0 = (w & 1) * 64;
    const int m0 = blockIdx.x * 128;

    float acc[2][8][4];
#pragma unroll
    for (int mi = 0; mi < 2; mi++)
#pragma unroll
        for (int j = 0; j < 8; j++)
#pragma unroll
            for (int r = 0; r < 4; r++) acc[mi][j][r] = 0.f;

    for (int kt = 0; kt < 8; kt++) {
#pragma unroll
        for (int i = 0; i < 4; i++) {
            int idx = tid + i * 256;
            int row = idx >> 3, c4 = idx & 7;
            *reinterpret_cast<float4*>(&Xs[row * 36 + c4 * 4]) =
                *reinterpret_cast<const float4*>(
                    &X[(size_t)(m0 + row) * DIN + kt * 32 + c4 * 4]);
        }
#pragma unroll
        for (int i = 0; i < 4; i++) {
            int idx = tid + i * 256;
            int row = idx >> 5, c = idx & 31;
            *reinterpret_cast<float4*>(&Ws[row * 136 + c * 4]) =
                *reinterpret_cast<const float4*>(
                    &W[(size_t)(kt * 32 + row) * DATT + c * 4]);
        }
        __syncthreads();

#pragma unroll
        for (int ks = 0; ks < 4; ks++) {
            int k0 = ks * 8;
            uint32_t a[2][4];
#pragma unroll
            for (int mi = 0; mi < 2; mi++) {
                int rr = r0 + 16 * mi + g;
                a[mi][0] = fu(Xs[rr * 36 + k0 + t]);
                a[mi][1] = fu(Xs[(rr + 8) * 36 + k0 + t]);
                a[mi][2] = fu(Xs[rr * 36 + k0 + t + 4]);
                a[mi][3] = fu(Xs[(rr + 8) * 36 + k0 + t + 4]);
            }
#pragma unroll
            for (int j = 0; j < 8; j++) {
                uint32_t b0 = fu(Ws[(k0 + t) * 136 + n0 + 8 * j + g]);
                uint32_t b1 = fu(Ws[(k0 + t + 4) * 136 + n0 + 8 * j + g]);
#pragma unroll
                for (int mi = 0; mi < 2; mi++)
                    mma8(acc[mi][j], a[mi][0], a[mi][1], a[mi][2], a[mi][3], b0, b1);
            }
        }
        __syncthreads();
    }

#pragma unroll
    for (int mi = 0; mi < 2; mi++) {
        float* O0 = O + (size_t)(m0 + r0 + 16 * mi + g) * DATT;
        float* O1 = O0 + (size_t)8 * DATT;
#pragma unroll
        for (int j = 0; j < 8; j++) {
            int cl = n0 + 8 * j + 2 * t;
            O0[ZP(cl)]     = f2tf(elu01(acc[mi][j][0]));
            O0[ZP(cl + 1)] = f2tf(elu01(acc[mi][j][1]));
            O1[ZP(cl)]     = f2tf(elu01(acc[mi][j][2]));
            O1[ZP(cl + 1)] = f2tf(elu01(acc[mi][j][3]));
        }
    }
}

// ---------------------------------------------------------------------------
// Kernel 2: fused flash attention, tf32 mma, zipped+swizzled operand tiles.
// grid = (16, 8), block = 512 (16 warps).
// Swizzle rule everywhere: float-index XOR ((row & 1) << 4).  Note row+8
// PRESERVES parity, so rows g and g+8 use the SAME swizzle (this was the
// round-6 bug: qb used the flipped swizzle).
// ---------------------------------------------------------------------------
#define TQ 128
#define TK 64
#define VP 264

#define OFF_Q   0
#define OFF_K   (OFF_Q + TQ * 128)   // 16384
#define OFF_V   (OFF_K + TK * 128)   // 24576
#define OFF_P   (OFF_V + TK * VP)    // 41472
#define OFF_L   (OFF_P + TQ * 64)    // 49664
#define OFF_MSK (OFF_L + 2 * TQ)     // 49920
#define SMEMF   (OFF_MSK + TK)       // 49984 floats
#define SMEMB   (SMEMF * 4)          // 199936 bytes

__global__ __launch_bounds__(512, 1) void attn_kernel(
    const float* __restrict__ qryV,
    const int*   __restrict__ qmask,
    float*       __restrict__ out)
{
    extern __shared__ float sm[];
    float* Qs   = sm + OFF_Q;
    float* Ks   = sm + OFF_K;
    float* Vs   = sm + OFF_V;
    float* Ps   = sm + OFF_P;
    float* redL = sm + OFF_L;
    int*   vmsk = reinterpret_cast<int*>(sm + OFF_MSK);
    const uint32_t smb = (uint32_t)__cvta_generic_to_shared(sm);

    const int b   = blockIdx.y;
    const int c0  = blockIdx.x * TQ;
    const int tid = threadIdx.x;
    const int w    = tid >> 5;
    const int lane = tid & 31;
    const int g = lane >> 2;
    const int t = lane & 3;
    const int wr  = w >> 1, wc  = w & 1;
    const int wr2 = w >> 2, wc2 = w & 3;
    const int r0  = wr * 16;
    const int nq0 = wc * 32;
    const int r2  = wr2 * 32;
    const int n2  = wc2 * 64;
    const int swe = (g & 1) << 4;   // swizzle for ALL rows (r0+g) and (r0+g+8)
    const float cs = 0.12751743f;   // (1/sqrt(128)) * log2(e)

    // prologue: Q tile via cp.async
#pragma unroll
    for (int i = 0; i < 8; i++) {
        int idx = tid + i * 512;
        int row = idx >> 5, c4 = idx & 31;
        uint32_t dst = smb + (uint32_t)(OFF_Q + row * 128 + ((c4 * 4) ^ ((row & 1) << 4))) * 4u;
        cpa16(dst, &g_inp[(size_t)(b * LL + c0 + row) * DATT + c4 * 4]);
    }
    CPA_COMMIT();

    float o[2][8][4];
#pragma unroll
    for (int mi = 0; mi < 2; mi++)
#pragma unroll
        for (int j = 0; j < 8; j++)
#pragma unroll
            for (int r = 0; r < 4; r++) o[mi][j][r] = 0.f;
    float lsum0 = 0.f, lsum1 = 0.f;

#pragma unroll 1
    for (int q0 = 0; q0 < LL; q0 += TK) {
        __syncthreads();

        // V tile LDGs first (latency overlaps the K cp.async below)
        float4 vv[8];
#pragma unroll
        for (int i = 0; i < 8; i++) {
            int idx = tid + i * 512;
            int vr = idx >> 6, v4 = idx & 63;
            vv[i] = *reinterpret_cast<const float4*>(
                &qryV[(size_t)(b * LL + q0 + vr) * DIN + v4 * 4]);
        }
        // K tile via cp.async
#pragma unroll
        for (int i = 0; i < 4; i++) {
            int idx = tid + i * 512;
            int row = idx >> 5, c4 = idx & 31;
            uint32_t dst = smb + (uint32_t)(OFF_K + row * 128 + ((c4 * 4) ^ ((row & 1) << 4))) * 4u;
            cpa16(dst, &g_mem[(size_t)(b * LL + q0 + row) * DATT + c4 * 4]);
        }
        CPA_COMMIT();
        int mv = 0;
        if (tid < TK) mv = qmask[b * LL + q0 + tid];
#pragma unroll
        for (int i = 0; i < 8; i++) {
            int idx = tid + i * 512;
            int vr = idx >> 6, v4 = idx & 63;
            float4 v = vv[i];
            v.x = f2tf(v.x); v.y = f2tf(v.y); v.z = f2tf(v.z); v.w = f2tf(v.w);
            *reinterpret_cast<float4*>(&Vs[vr * VP + v4 * 4]) = v;
        }
        if (tid < TK) vmsk[tid] = mv;
        CPA_WAIT0();
        __syncthreads();

        // ---- GEMM1: S[128,64] = Q.K^T (zipped LDS.128 fragments) ----
        float s[4][4];
#pragma unroll
        for (int j = 0; j < 4; j++)
#pragma unroll
            for (int r = 0; r < 4; r++) s[j][r] = 0.f;

        const int qr0 = (r0 + g) * 128;
        const int qr1 = (r0 + g + 8) * 128;
#pragma unroll
        for (int s2 = 0; s2 < 8; s2++) {
            int col = (s2 * 16 + t * 4) ^ swe;
            float4 qa = *reinterpret_cast<const float4*>(&Qs[qr0 + col]);
            float4 qb = *reinterpret_cast<const float4*>(&Qs[qr1 + col]);
            float4 kb[4];
#pragma unroll
            for (int j = 0; j < 4; j++)
                kb[j] = *reinterpret_cast<const float4*>(
                    &Ks[(nq0 + 8 * j + g) * 128 + col]);
#pragma unroll
            for (int j = 0; j < 4; j++)
                mma8(s[j], fu(qa.x), fu(qb.x), fu(qa.y), fu(qb.y), fu(kb[j].x), fu(kb[j].y));
#pragma unroll
            for (int j = 0; j < 4; j++)
                mma8(s[j], fu(qa.z), fu(qb.z), fu(qa.w), fu(qb.w), fu(kb[j].z), fu(kb[j].w));
        }

        // ---- fixed-max softmax, store P zipped (parity swizzle) ----
        {
            const int cg0 = c0 + r0 + g, cg1 = cg0 + 8;
            const int pr0 = (r0 + g) * 64;
            const int pr1 = (r0 + g + 8) * 64;
            float su0 = 0.f, su1 = 0.f;
#pragma unroll
            for (int j = 0; j < 4; j++) {
                int cl = nq0 + 8 * j + 2 * t;
                bool v0 = vmsk[cl] > 0, v1 = vmsk[cl + 1] > 0;
                int qg0 = q0 + cl, qg1 = qg0 + 1;
                float p00 = (v0 && cg0 != qg0) ? fex2(s[j][0] * cs) : 0.f;
                float p01 = (v1 && cg0 != qg1) ? fex2(s[j][1] * cs) : 0.f;
                float p10 = (v0 && cg1 != qg0) ? fex2(s[j][2] * cs) : 0.f;
                float p11 = (v1 && cg1 != qg1) ? fex2(s[j][3] * cs) : 0.f;
                su0 += p00 + p01;
                su1 += p10 + p11;
                int z0 = ZP(cl), z1 = ZP(cl + 1);
                Ps[pr0 + (z0 ^ swe)] = f2tf(p00);
                Ps[pr0 + (z1 ^ swe)] = f2tf(p01);
                Ps[pr1 + (z0 ^ swe)] = f2tf(p10);
                Ps[pr1 + (z1 ^ swe)] = f2tf(p11);
            }
            su0 += __shfl_xor_sync(0xffffffffu, su0, 1);
            su0 += __shfl_xor_sync(0xffffffffu, su0, 2);
            su1 += __shfl_xor_sync(0xffffffffu, su1, 1);
            su1 += __shfl_xor_sync(0xffffffffu, su1, 2);
            lsum0 += su0;
            lsum1 += su1;
        }
        __syncthreads();

        // ---- GEMM2: O[128,256] += P . V ----
        const int ar0 = (r2 + g) * 64;
        const int ar1 = (r2 + g + 8) * 64;
        const int ar2 = (r2 + 16 + g) * 64;
        const int ar3 = (r2 + 24 + g) * 64;
#pragma unroll
        for (int s2 = 0; s2 < 4; s2++) {
            int col = (s2 * 16 + t * 4) ^ swe;
            float4 pa0 = *reinterpret_cast<const float4*>(&Ps[ar0 + col]);
            float4 pb0 = *reinterpret_cast<const float4*>(&Ps[ar1 + col]);
            float4 pa1 = *reinterpret_cast<const float4*>(&Ps[ar2 + col]);
            float4 pb1 = *reinterpret_cast<const float4*>(&Ps[ar3 + col]);
            int k0 = s2 * 16;
#pragma unroll
            for (int j = 0; j < 8; j++) {
                uint32_t b0 = fu(Vs[(k0 + t) * VP + n2 + 8 * j + g]);
                uint32_t b1 = fu(Vs[(k0 + t + 4) * VP + n2 + 8 * j + g]);
                mma8(o[0][j], fu(pa0.x), fu(pb0.x), fu(pa0.y), fu(pb0.y), b0, b1);
                mma8(o[1][j], fu(pa1.x), fu(pb1.x), fu(pa1.y), fu(pb1.y), b0, b1);
            }
#pragma unroll
            for (int j = 0; j < 8; j++) {
                uint32_t b0 = fu(Vs[(k0 + 8 + t) * VP + n2 + 8 * j + g]);
                uint32_t b1 = fu(Vs[(k0 + 12 + t) * VP + n2 + 8 * j + g]);
                mma8(o[0][j], fu(pa0.z), fu(pb0.z), fu(pa0.w), fu(pb0.w), b0, b1);
                mma8(o[1][j], fu(pa1.z), fu(pb1.z), fu(pa1.w), fu(pb1.w), b0, b1);
            }
        }
    }

    if (t == 0) {
        redL[wc * TQ + r0 + g]     = lsum0;
        redL[wc * TQ + r0 + g + 8] = lsum1;
    }
    __syncthreads();

#pragma unroll
    for (int mi = 0; mi < 2; mi++) {
        int rr0 = r2 + 16 * mi + g;
        int rr1 = rr0 + 8;
        float l0 = 1.0f / (redL[rr0] + redL[TQ + rr0]);
        float l1 = 1.0f / (redL[rr1] + redL[TQ + rr1]);
        size_t rb0 = (size_t)(b * LL + c0 + rr0) * DIN;
        size_t rb1 = (size_t)(b * LL + c0 + rr1) * DIN;
#pragma unroll
        for (int j = 0; j < 8; j++) {
            int cl = n2 + 8 * j + 2 * t;
            *reinterpret_cast<float2*>(&out[rb0 + cl]) =
                make_float2(o[mi][j][0] * l0, o[mi][j][1] * l0);
            *reinterpret_cast<float2*>(&out[rb1 + cl]) =
                make_float2(o[mi][j][2] * l1, o[mi][j][3] * l1);
        }
    }
}

// ---------------------------------------------------------------------------
extern "C" void kernel_launch(void* const* d_in, const int* in_sizes, int n_in,
                              void* d_out, int out_size)
{
    const float* ctx  = (const float*)d_in[0];
    const float* qry  = (const float*)d_in[1];
    const float* Win  = (const float*)d_in[2];
    const float* Wmem = (const float*)d_in[3];
    const int*   msk  = (const int*)d_in[4];
    float* out = (float*)d_out;

    (void)in_sizes; (void)n_in; (void)out_size;

    cudaFuncSetAttribute(attn_kernel,
                         cudaFuncAttributeMaxDynamicSharedMemorySize, SMEMB);

    proj_kernel<<<dim3(BB * LL / 128, 2), 256>>>(ctx, qry, Win, Wmem);
    attn_kernel<<<dim3(LL / TQ, BB), 512, SMEMB>>>(qry, msk, out);
}